// round 9
// baseline (speedup 1.0000x reference)
#include <cuda_runtime.h>
#include <cuda_bf16.h>

#define BINS 32
#define CZ   128
#define NCLS 66              // 2*BINS + 2
#define LSEQ 768
#define NB   2
#define TPB  256
#define NCTAS (148 * 5)      // persistent grid: 5 CTAs/SM x 148 SMs
#define JCHUNK 96            // j-vectors per work chunk
#define NCHUNK (NB * LSEQ * (LSEQ / JCHUNK))   // 12288

// CONVERGED FINAL (98.8us, ~6.0 TB/s effective — ~95% of the measured LTS
// write-path ceiling). Persistent-CTA kernel: each CTA builds Wb=W+b (row 0
// zeroed = mask sink for idx in [1,65]), caches residue/mask rows for both
// batches, then grid-strides over 12288 (row, j-block) chunks. Each warp
// stores one C_Z=128 float vector per j as LDS.128 -> STG.E.128 (.cs
// streaming), serial per-warp store stream (unroll>=2 is neutral, unroll 4
// regresses via L1tex queue contention; higher occupancy is neutral-to-worse;
// write-back L2 regresses 16%).
__global__ __launch_bounds__(TPB) void relpos_kernel(
    const int*   __restrict__ ridx,   // [B, L] int32
    const int*   __restrict__ rmask,  // [B, L] bool widened to int32
    const float* __restrict__ W,      // [66, 128]
    const float* __restrict__ bias,   // [128]
    float*       __restrict__ out)    // [B, L, L, 128]
{
    __shared__ float         wb[NCLS * CZ];    // 33792 B; row 0 = zeros
    __shared__ int           rj[NB * LSEQ];    // 6144 B
    __shared__ unsigned char mj[NB * LSEQ];    // 1536 B

    const int tid = threadIdx.x;

    // Wb table: row 0 (unused by valid classes, idx in [1,65]) = zeros
    #pragma unroll 4
    for (int k = tid; k < NCLS * CZ; k += TPB)
        wb[k] = (k < CZ) ? 0.0f : (W[k] + bias[k & (CZ - 1)]);

    for (int k = tid; k < NB * LSEQ; k += TPB) {
        rj[k] = ridx[k];
        mj[k] = (unsigned char)(rmask[k] != 0);
    }
    __syncthreads();

    const int lane = tid & 31;
    const int warp = tid >> 5;

    for (int c = blockIdx.x; c < NCHUNK; c += NCTAS) {
        const int row   = c >> 3;               // 0 .. B*L-1   (8 chunks/row)
        const int jbase = (c & 7) * JCHUNK;
        const int b     = row / LSEQ;
        const int i     = row - b * LSEQ;
        const int boff  = b * LSEQ;
        const int ri    = rj[boff + i];
        const bool mi   = (mj[boff + i] != 0);

        float4* orow = reinterpret_cast<float4*>(out)
                     + (size_t)row * LSEQ * (CZ / 4);

        // 96 j's / 8 warps = 12 iterations per warp, serial store stream
        #pragma unroll 1
        for (int t = warp; t < JCHUNK; t += TPB / 32) {
            const int j = jbase + t;
            int d = rj[boff + j] - ri;
            d = min(max(d, -BINS), BINS) + BINS + 1;      // [1, 65]
            if (!(mi && (mj[boff + j] != 0))) d = 0;      // masked -> zero row
            float4 v = *reinterpret_cast<const float4*>(&wb[d * CZ + lane * 4]);
            __stcs(&orow[(size_t)j * (CZ / 4) + lane], v);
        }
    }
}

extern "C" void kernel_launch(void* const* d_in, const int* in_sizes, int n_in,
                              void* d_out, int out_size) {
    const int*   ridx  = (const int*)d_in[0];
    const int*   rmask = (const int*)d_in[1];
    const float* W     = (const float*)d_in[2];
    const float* bias  = (const float*)d_in[3];
    float*       out   = (float*)d_out;

    relpos_kernel<<<NCTAS, TPB>>>(ridx, rmask, W, bias, out);
}

// round 10
// speedup vs baseline: 1.0111x; 1.0111x over previous
#include <cuda_runtime.h>
#include <cuda_bf16.h>

#define BINS 32
#define CZ   128
#define NCLS 66              // 2*BINS + 2
#define LSEQ 768
#define NB   2
#define TPB  1024            // 32 warps, one CTA per SM
#define NCTAS 148            // exactly one concurrent write stream per SM
#define JCHUNK 96            // j-vectors per work chunk (48KB contiguous)
#define NCHUNK (NB * LSEQ * (LSEQ / JCHUNK))   // 12288

// Stream-locality experiment: 148 persistent CTAs (1/SM), 32 warps each, all
// warps of a CTA writing inside the same contiguous 48KB chunk window at once.
// Cuts chip-wide concurrent DRAM write streams 740 -> 148 for longer same-row
// bursts per bank. Value path unchanged: smem Wb=W+b table (row 0 = mask
// sink), per-warp LDS.128 -> STG.E.128 (.cs streaming), serial store stream.
__global__ __launch_bounds__(TPB) void relpos_kernel(
    const int*   __restrict__ ridx,   // [B, L] int32
    const int*   __restrict__ rmask,  // [B, L] bool widened to int32
    const float* __restrict__ W,      // [66, 128]
    const float* __restrict__ bias,   // [128]
    float*       __restrict__ out)    // [B, L, L, 128]
{
    __shared__ float         wb[NCLS * CZ];    // 33792 B; row 0 = zeros
    __shared__ int           rj[NB * LSEQ];    // 6144 B
    __shared__ unsigned char mj[NB * LSEQ];    // 1536 B

    const int tid = threadIdx.x;

    // Wb table: row 0 (unused by valid classes, idx in [1,65]) = zeros
    #pragma unroll 2
    for (int k = tid; k < NCLS * CZ; k += TPB)
        wb[k] = (k < CZ) ? 0.0f : (W[k] + bias[k & (CZ - 1)]);

    for (int k = tid; k < NB * LSEQ; k += TPB) {
        rj[k] = ridx[k];
        mj[k] = (unsigned char)(rmask[k] != 0);
    }
    __syncthreads();

    const int lane = tid & 31;
    const int warp = tid >> 5;

    for (int c = blockIdx.x; c < NCHUNK; c += NCTAS) {
        const int row   = c >> 3;               // 0 .. B*L-1   (8 chunks/row)
        const int jbase = (c & 7) * JCHUNK;
        const int b     = row / LSEQ;
        const int i     = row - b * LSEQ;
        const int boff  = b * LSEQ;
        const int ri    = rj[boff + i];
        const bool mi   = (mj[boff + i] != 0);

        float4* orow = reinterpret_cast<float4*>(out)
                     + (size_t)row * LSEQ * (CZ / 4);

        // 96 j's / 32 warps = 3 iterations per warp, all inside one 48KB window
        #pragma unroll 1
        for (int t = warp; t < JCHUNK; t += TPB / 32) {
            const int j = jbase + t;
            int d = rj[boff + j] - ri;
            d = min(max(d, -BINS), BINS) + BINS + 1;      // [1, 65]
            if (!(mi && (mj[boff + j] != 0))) d = 0;      // masked -> zero row
            float4 v = *reinterpret_cast<const float4*>(&wb[d * CZ + lane * 4]);
            __stcs(&orow[(size_t)j * (CZ / 4) + lane], v);
        }
    }
}

extern "C" void kernel_launch(void* const* d_in, const int* in_sizes, int n_in,
                              void* d_out, int out_size) {
    const int*   ridx  = (const int*)d_in[0];
    const int*   rmask = (const int*)d_in[1];
    const float* W     = (const float*)d_in[2];
    const float* bias  = (const float*)d_in[3];
    float*       out   = (float*)d_out;

    relpos_kernel<<<NCTAS, TPB>>>(ridx, rmask, W, bias, out);
}

// round 11
// speedup vs baseline: 1.0309x; 1.0196x over previous
#include <cuda_runtime.h>
#include <cuda_bf16.h>
#include <cstdint>

#define BINS 32
#define CZ   128
#define NCLS 66              // 2*BINS + 2
#define LSEQ 768
#define NB   2
#define TPB  1024            // 32 warps, one CTA per SM
#define NCTAS 148
#define JCHUNK 96            // j-vectors per chunk = 96*512B = 48KB
#define CHUNK_FLOATS (JCHUNK * CZ)             // 12288 floats
#define CHUNK_BYTES  (CHUNK_FLOATS * 4)        // 49152
#define NCHUNK (NB * LSEQ * (LSEQ / JCHUNK))   // 12288

// dynamic smem layout (bytes):
//   [0, 33792)            wb  (66*128 floats; row 0 = zeros = mask sink)
//   [33792, 33792+98304)  stage[2] double buffer (2 x 48KB)
//   [132096, 138240)      rj  (1536 ints)
//   [138240, 139776)      mj  (1536 bytes)
#define OFF_WB    0
#define OFF_STAGE 33792
#define OFF_RJ    (OFF_STAGE + 2 * CHUNK_BYTES)
#define OFF_MJ    (OFF_RJ + NB * LSEQ * 4)
#define SMEM_TOTAL (OFF_MJ + NB * LSEQ)

// Bulk-store experiment: compute each 48KB chunk into a smem staging buffer,
// then push it to GMEM with ONE cp.async.bulk (1-D, no tensormap) so the DRAM
// controller sees whole-chunk burst descriptors instead of per-warp STG
// wavefronts. Double-buffered so chunk c+1 compute overlaps chunk c's drain.
__global__ __launch_bounds__(TPB) void relpos_kernel(
    const int*   __restrict__ ridx,
    const int*   __restrict__ rmask,
    const float* __restrict__ W,
    const float* __restrict__ bias,
    float*       __restrict__ out)
{
    extern __shared__ char smem[];
    float*         wb    = reinterpret_cast<float*>(smem + OFF_WB);
    float*         stage = reinterpret_cast<float*>(smem + OFF_STAGE);
    int*           rj    = reinterpret_cast<int*>(smem + OFF_RJ);
    unsigned char* mj    = reinterpret_cast<unsigned char*>(smem + OFF_MJ);

    const int tid = threadIdx.x;

    #pragma unroll 2
    for (int k = tid; k < NCLS * CZ; k += TPB)
        wb[k] = (k < CZ) ? 0.0f : (W[k] + bias[k & (CZ - 1)]);

    for (int k = tid; k < NB * LSEQ; k += TPB) {
        rj[k] = ridx[k];
        mj[k] = (unsigned char)(rmask[k] != 0);
    }
    __syncthreads();

    const int lane = tid & 31;
    const int warp = tid >> 5;

    uint32_t stage_u32;
    asm("{ .reg .u64 t; cvta.to.shared.u64 t, %1; cvt.u32.u64 %0, t; }"
        : "=r"(stage_u32) : "l"(stage));

    int it = 0;
    for (int c = blockIdx.x; c < NCHUNK; c += NCTAS, it++) {
        const int buf = it & 1;
        float4* sbuf = reinterpret_cast<float4*>(stage + buf * CHUNK_FLOATS);

        // Before overwriting this buffer, make sure the bulk store issued two
        // iterations ago (which read it) has finished its smem reads.
        if (it >= 2 && tid == 0)
            asm volatile("cp.async.bulk.wait_group.read 1;" ::: "memory");
        __syncthreads();

        const int row   = c >> 3;
        const int jbase = (c & 7) * JCHUNK;
        const int b     = row / LSEQ;
        const int i     = row - b * LSEQ;
        const int boff  = b * LSEQ;
        const int ri    = rj[boff + i];
        const bool mi   = (mj[boff + i] != 0);

        // 96 j's / 32 warps = 3 per warp; write into staging buffer
        #pragma unroll 3
        for (int t = warp; t < JCHUNK; t += TPB / 32) {
            const int j = jbase + t;
            int d = rj[boff + j] - ri;
            d = min(max(d, -BINS), BINS) + BINS + 1;      // [1, 65]
            if (!(mi && (mj[boff + j] != 0))) d = 0;      // masked -> zero row
            float4 v = *reinterpret_cast<const float4*>(&wb[d * CZ + lane * 4]);
            sbuf[t * 32 + lane] = v;
        }
        __syncthreads();

        if (tid == 0) {
            asm volatile("fence.proxy.async.shared::cta;" ::: "memory");
            const float* dst = out + (size_t)row * LSEQ * CZ + (size_t)jbase * CZ;
            asm volatile(
                "cp.async.bulk.global.shared::cta.bulk_group [%0], [%1], %2;"
                :: "l"(dst), "r"(stage_u32 + buf * CHUNK_BYTES), "n"(CHUNK_BYTES)
                : "memory");
            asm volatile("cp.async.bulk.commit_group;" ::: "memory");
        }
    }

    // Drain all outstanding bulk stores before exit.
    if (tid == 0)
        asm volatile("cp.async.bulk.wait_group 0;" ::: "memory");
}

extern "C" void kernel_launch(void* const* d_in, const int* in_sizes, int n_in,
                              void* d_out, int out_size) {
    const int*   ridx  = (const int*)d_in[0];
    const int*   rmask = (const int*)d_in[1];
    const float* W     = (const float*)d_in[2];
    const float* bias  = (const float*)d_in[3];
    float*       out   = (float*)d_out;

    static int configured = 0;
    if (!configured) {
        cudaFuncSetAttribute(relpos_kernel,
                             cudaFuncAttributeMaxDynamicSharedMemorySize,
                             SMEM_TOTAL);
        configured = 1;
    }
    relpos_kernel<<<NCTAS, TPB, SMEM_TOTAL>>>(ridx, rmask, W, bias, out);
}